// round 2
// baseline (speedup 1.0000x reference)
#include <cuda_runtime.h>
#include <cuda_bf16.h>

// ProbabilityAdjustedLoss: B=8388608 rows, logits [B,2] fp32, labels [B] int32
// (JAX w/o x64 downcasts jnp.int64 -> int32 on device).
// Pure HBM-bound streaming reduction: 96 MiB in, 4 B out.
//
// Kernel 1: grid-stride, 4 rows per iteration (2x float4 logits + 1x int4 labels),
//           per-block partial sums -> __device__ scratch (no allocations).
// Kernel 2: single block reduces partials, writes mean. Deterministic.

#define BASE_STABLE 0.95f
#define BASE_CHANGE 0.05f
#define EPS_LOSS 1e-8f

#define NBLOCKS 2048
#define NTHREADS 256

__device__ float g_partials[NBLOCKS];

__device__ __forceinline__ float row_loss(float l0, float l1, int lab) {
    // p_selected = softmax probability of the labeled class:
    //   label==0: p0 = 1/(1 + exp(l1 - l0))
    //   label==1: p1 = 1/(1 + exp(l0 - l1))
    const bool stable = (lab == 0);
    const float x = stable ? (l1 - l0) : (l0 - l1);
    const float p = 1.0f / (1.0f + __expf(x));

    float w;
    if (stable) {
        const float adj = fmaxf(0.0f, p - BASE_STABLE) * (1.0f / (1.0f - BASE_STABLE));
        w = fmaxf(0.1f, 1.0f - 0.5f * adj);
    } else {
        const float adj = fmaxf(0.0f, p - BASE_CHANGE) * (1.0f / (1.0f - BASE_CHANGE));
        w = fmaxf(0.5f, 2.0f - adj);
    }
    return -w * __logf(p + EPS_LOSS);
}

__global__ void __launch_bounds__(NTHREADS)
loss_partial_kernel(const float4* __restrict__ logits2,  // 2 rows per float4
                    const int4* __restrict__ labels4,    // 4 labels per int4
                    int nquads) {                        // groups of 4 rows
    float acc = 0.0f;
    const int stride = gridDim.x * blockDim.x;
    for (int i = blockIdx.x * blockDim.x + threadIdx.x; i < nquads; i += stride) {
        const float4 lgA = logits2[2 * i + 0];
        const float4 lgB = logits2[2 * i + 1];
        const int4   lb  = labels4[i];
        acc += row_loss(lgA.x, lgA.y, lb.x);
        acc += row_loss(lgA.z, lgA.w, lb.y);
        acc += row_loss(lgB.x, lgB.y, lb.z);
        acc += row_loss(lgB.z, lgB.w, lb.w);
    }

    // Block reduction
    __shared__ float sdata[NTHREADS];
    sdata[threadIdx.x] = acc;
    __syncthreads();
    #pragma unroll
    for (int s = NTHREADS / 2; s > 32; s >>= 1) {
        if (threadIdx.x < s) sdata[threadIdx.x] += sdata[threadIdx.x + s];
        __syncthreads();
    }
    if (threadIdx.x < 32) {
        float v = sdata[threadIdx.x] + sdata[threadIdx.x + 32];
        #pragma unroll
        for (int off = 16; off > 0; off >>= 1)
            v += __shfl_down_sync(0xFFFFFFFFu, v, off);
        if (threadIdx.x == 0) g_partials[blockIdx.x] = v;
    }
}

__global__ void __launch_bounds__(1024)
final_reduce_kernel(float* __restrict__ out, float inv_B) {
    __shared__ float sdata[1024];
    float v = 0.0f;
    for (int i = threadIdx.x; i < NBLOCKS; i += 1024) v += g_partials[i];
    sdata[threadIdx.x] = v;
    __syncthreads();
    #pragma unroll
    for (int s = 512; s > 32; s >>= 1) {
        if (threadIdx.x < s) sdata[threadIdx.x] += sdata[threadIdx.x + s];
        __syncthreads();
    }
    if (threadIdx.x < 32) {
        float w = sdata[threadIdx.x] + sdata[threadIdx.x + 32];
        #pragma unroll
        for (int off = 16; off > 0; off >>= 1)
            w += __shfl_down_sync(0xFFFFFFFFu, w, off);
        if (threadIdx.x == 0) out[0] = w * inv_B;
    }
}

extern "C" void kernel_launch(void* const* d_in, const int* in_sizes, int n_in,
                              void* d_out, int out_size) {
    const float4* logits2 = (const float4*)d_in[0];  // [B,2] fp32 -> B/2 float4
    const int4*   labels4 = (const int4*)d_in[1];    // [B] int32 -> B/4 int4
    const int B = in_sizes[1];                       // label element count
    const int nquads = B / 4;                        // B = 8388608, divisible by 4

    loss_partial_kernel<<<NBLOCKS, NTHREADS>>>(logits2, labels4, nquads);
    final_reduce_kernel<<<1, 1024>>>((float*)d_out, 1.0f / (float)B);
}